// round 5
// baseline (speedup 1.0000x reference)
#include <cuda_runtime.h>
#include <cuda_bf16.h>
#include <math.h>

#define NUM_ENT 14541
#define EMBED_DIM 200
#define BATCH 256
#define GAMMA 9.0f

// Scratch for obj = ent[sub] + rel[rel]  (256 x 200 fp32 = 200 KB)
__device__ float g_obj[BATCH * EMBED_DIM];

__global__ void obj_kernel(const float* __restrict__ ent,
                           const float* __restrict__ relE,
                           const int* __restrict__ sub,
                           const int* __restrict__ rel) {
    int b = blockIdx.x;
    int s = sub[b];
    int r = rel[b];
    for (int d = threadIdx.x; d < EMBED_DIM; d += blockDim.x) {
        g_obj[b * EMBED_DIM + d] = ent[s * EMBED_DIM + d] + relE[r * EMBED_DIM + d];
    }
}

// Single-warp CTA: tile 32(b) x 64(n), 32 threads, 8x8 register micro-tile.
// K-chunk = 8, double-buffered smem (transposed [k][col]), one __syncwarp per chunk.
// Grid = (8 b-tiles, 228 n-tiles) = 1824 warps -> 12.3/SM (fine-grained balance).
__global__ __launch_bounds__(32, 13)
void score_kernel(const float* __restrict__ ent, float* __restrict__ out) {
    __shared__ __align__(16) float ent_s[2][8][68];  // [buf][k][n-col], pad 68
    __shared__ __align__(16) float obj_s[2][8][36];  // [buf][k][b-col], pad 36

    const int b0 = blockIdx.x * 32;
    const int n0 = blockIdx.y * 64;
    const int t  = threadIdx.x;     // 0..31
    const int bg = t >> 3;          // 0..3  (b-groups)
    const int ng = t & 7;           // 0..7  (n-groups)

    // loader roles (per thread): obj row b0+t; ent rows n0+t, n0+t+32 (clamped)
    const size_t er0 = (size_t)min(n0 + t,      NUM_ENT - 1);
    const size_t er1 = (size_t)min(n0 + t + 32, NUM_ENT - 1);

    const float* obj_src  = &g_obj[(b0 + t) * EMBED_DIM];
    const float* ent_src0 = &ent[er0 * EMBED_DIM];
    const float* ent_src1 = &ent[er1 * EMBED_DIM];

    float acc[8][8];
#pragma unroll
    for (int i = 0; i < 8; i++)
#pragma unroll
        for (int j = 0; j < 8; j++) acc[i][j] = 0.0f;

    // ---- load chunk 0 into buffer 0 ----
    {
        float4 ov0 = *(const float4*)(obj_src + 0);
        float4 ov1 = *(const float4*)(obj_src + 4);
        float4 e00 = *(const float4*)(ent_src0 + 0);
        float4 e01 = *(const float4*)(ent_src0 + 4);
        float4 e10 = *(const float4*)(ent_src1 + 0);
        float4 e11 = *(const float4*)(ent_src1 + 4);
        obj_s[0][0][t] = ov0.x; obj_s[0][1][t] = ov0.y;
        obj_s[0][2][t] = ov0.z; obj_s[0][3][t] = ov0.w;
        obj_s[0][4][t] = ov1.x; obj_s[0][5][t] = ov1.y;
        obj_s[0][6][t] = ov1.z; obj_s[0][7][t] = ov1.w;
        ent_s[0][0][t] = e00.x; ent_s[0][1][t] = e00.y;
        ent_s[0][2][t] = e00.z; ent_s[0][3][t] = e00.w;
        ent_s[0][4][t] = e01.x; ent_s[0][5][t] = e01.y;
        ent_s[0][6][t] = e01.z; ent_s[0][7][t] = e01.w;
        ent_s[0][0][t + 32] = e10.x; ent_s[0][1][t + 32] = e10.y;
        ent_s[0][2][t + 32] = e10.z; ent_s[0][3][t + 32] = e10.w;
        ent_s[0][4][t + 32] = e11.x; ent_s[0][5][t + 32] = e11.y;
        ent_s[0][6][t + 32] = e11.z; ent_s[0][7][t + 32] = e11.w;
    }
    __syncwarp();

    const int NITER = EMBED_DIM / 8;  // 25
#pragma unroll 1
    for (int it = 0; it < NITER; ++it) {
        const int cur = it & 1;

        // prefetch next K-chunk into registers (overlaps with compute)
        float4 pov0, pov1, pe00, pe01, pe10, pe11;
        const bool have_next = (it + 1 < NITER);
        if (have_next) {
            const int kk = (it + 1) * 8;
            pov0 = *(const float4*)(obj_src + kk);
            pov1 = *(const float4*)(obj_src + kk + 4);
            pe00 = *(const float4*)(ent_src0 + kk);
            pe01 = *(const float4*)(ent_src0 + kk + 4);
            pe10 = *(const float4*)(ent_src1 + kk);
            pe11 = *(const float4*)(ent_src1 + kk + 4);
        }

#pragma unroll
        for (int k = 0; k < 8; ++k) {
            float4 a0 = *(const float4*)&obj_s[cur][k][bg * 4];
            float4 a1 = *(const float4*)&obj_s[cur][k][16 + bg * 4];
            float4 c0 = *(const float4*)&ent_s[cur][k][ng * 4];
            float4 c1 = *(const float4*)&ent_s[cur][k][32 + ng * 4];
            float av[8] = {a0.x, a0.y, a0.z, a0.w, a1.x, a1.y, a1.z, a1.w};
            float bv[8] = {c0.x, c0.y, c0.z, c0.w, c1.x, c1.y, c1.z, c1.w};
#pragma unroll
            for (int i = 0; i < 8; i++)
#pragma unroll
                for (int j = 0; j < 8; j++)
                    acc[i][j] += fabsf(av[i] - bv[j]);
        }

        if (have_next) {
            const int nxt = cur ^ 1;
            obj_s[nxt][0][t] = pov0.x; obj_s[nxt][1][t] = pov0.y;
            obj_s[nxt][2][t] = pov0.z; obj_s[nxt][3][t] = pov0.w;
            obj_s[nxt][4][t] = pov1.x; obj_s[nxt][5][t] = pov1.y;
            obj_s[nxt][6][t] = pov1.z; obj_s[nxt][7][t] = pov1.w;
            ent_s[nxt][0][t] = pe00.x; ent_s[nxt][1][t] = pe00.y;
            ent_s[nxt][2][t] = pe00.z; ent_s[nxt][3][t] = pe00.w;
            ent_s[nxt][4][t] = pe01.x; ent_s[nxt][5][t] = pe01.y;
            ent_s[nxt][6][t] = pe01.z; ent_s[nxt][7][t] = pe01.w;
            ent_s[nxt][0][t + 32] = pe10.x; ent_s[nxt][1][t + 32] = pe10.y;
            ent_s[nxt][2][t + 32] = pe10.z; ent_s[nxt][3][t + 32] = pe10.w;
            ent_s[nxt][4][t + 32] = pe11.x; ent_s[nxt][5][t + 32] = pe11.y;
            ent_s[nxt][6][t + 32] = pe11.z; ent_s[nxt][7][t + 32] = pe11.w;
        }
        __syncwarp();
    }

    // epilogue: score = 1 / (1 + exp(dist - GAMMA))
#pragma unroll
    for (int i = 0; i < 8; ++i) {
        const int b = b0 + bg * 4 + (i & 3) + 16 * (i >> 2);
        const size_t rowoff = (size_t)b * NUM_ENT;
#pragma unroll
        for (int j = 0; j < 8; ++j) {
            const int n = n0 + ng * 4 + (j & 3) + 32 * (j >> 2);
            if (n < NUM_ENT) {
                out[rowoff + n] = 1.0f / (1.0f + __expf(acc[i][j] - GAMMA));
            }
        }
    }
}

extern "C" void kernel_launch(void* const* d_in, const int* in_sizes, int n_in,
                              void* d_out, int out_size) {
    const float* ent  = (const float*)d_in[0];   // [14541, 200]
    const float* relE = (const float*)d_in[1];   // [474, 200]
    const int*   sub  = (const int*)d_in[2];     // [256]
    const int*   rel  = (const int*)d_in[3];     // [256]
    // d_in[4] = neg_ents: unused by the reference
    float* out = (float*)d_out;                  // [256, 14541]

    obj_kernel<<<BATCH, 128>>>(ent, relE, sub, rel);

    // x = b-tile (fast) so consecutive CTAs share the same ent n-tile in L2
    dim3 grid(BATCH / 32, (NUM_ENT + 63) / 64);  // (8, 228) = 1824 CTAs
    score_kernel<<<grid, 32>>>(ent, out);
}